// round 1
// baseline (speedup 1.0000x reference)
#include <cuda_runtime.h>

// Problem dims (fixed by setup_inputs)
#define Bv   1024
#define Tv   80
#define Dv   300
#define Hv   300
#define G4   1200           // 4*H
#define MROWS (Bv * Tv)     // 81920

// Scratch (device globals — no allocation allowed)
__device__ float g_xpre[(size_t)MROWS * G4];   // 393 MB: x@Wx + b for all (b,t)
__device__ float g_h[2][Bv * Hv];              // double-buffered hidden state
__device__ float g_c[Bv * Hv];                 // cell state

// ---------------------------------------------------------------------------
// Zero-init h (both buffers) and c
// ---------------------------------------------------------------------------
__global__ void zero_kernel() {
    int i = blockIdx.x * blockDim.x + threadIdx.x;
    if (i < Bv * Hv) {
        g_h[0][i] = 0.f;
        g_h[1][i] = 0.f;
        g_c[i]    = 0.f;
    }
}

// ---------------------------------------------------------------------------
// Precompute: g_xpre[r, n] = sum_k emb[sent[r], k] * Wx[k, n] + bias[n]
// r = b*T + t.  Tiles: BM=128 rows, BN=128 cols, KT=20. 256 threads, 8x8/thread.
// Early-exit when every row of the tile is masked (t >= lens[b]).
// ---------------------------------------------------------------------------
__global__ __launch_bounds__(256) void pre_kernel(
    const int*   __restrict__ sent,
    const int*   __restrict__ lens,
    const float* __restrict__ emb,
    const float* __restrict__ Wx,
    const float* __restrict__ bias)
{
    __shared__ int   idxs[128];
    __shared__ float es[20][128];
    __shared__ float ws[20][128];

    const int r0  = blockIdx.x * 128;
    const int n0  = blockIdx.y * 128;
    const int tid = threadIdx.x;
    const int tx  = tid & 15;
    const int ty  = tid >> 4;

    int flag = 0;
    if (tid < 128) {
        int row = r0 + tid;
        idxs[tid] = sent[row];
        int b = row / Tv;
        int t = row - b * Tv;
        flag = (t < lens[b]);
    }
    if (!__syncthreads_or(flag)) return;   // whole tile masked -> never used

    float acc[8][8];
#pragma unroll
    for (int i = 0; i < 8; i++)
#pragma unroll
        for (int j = 0; j < 8; j++) acc[i][j] = 0.f;

    for (int k0 = 0; k0 < Dv; k0 += 20) {
#pragma unroll
        for (int r = 0; r < 10; r++) {
            int f  = r * 256 + tid;
            int rl = f & 127;
            int kl = f >> 7;
            es[kl][rl] = emb[(size_t)idxs[rl] * Dv + k0 + kl];
            int n = n0 + rl;
            ws[kl][rl] = (n < G4) ? Wx[(k0 + kl) * G4 + n] : 0.f;
        }
        __syncthreads();
#pragma unroll
        for (int k = 0; k < 20; k++) {
            float4 a0 = *(const float4*)&es[k][ty * 4];
            float4 a1 = *(const float4*)&es[k][ty * 4 + 64];
            float4 w0 = *(const float4*)&ws[k][tx * 4];
            float4 w1 = *(const float4*)&ws[k][tx * 4 + 64];
            float a[8] = {a0.x, a0.y, a0.z, a0.w, a1.x, a1.y, a1.z, a1.w};
            float w[8] = {w0.x, w0.y, w0.z, w0.w, w1.x, w1.y, w1.z, w1.w};
#pragma unroll
            for (int i = 0; i < 8; i++)
#pragma unroll
                for (int j = 0; j < 8; j++)
                    acc[i][j] = fmaf(a[i], w[j], acc[i][j]);
        }
        __syncthreads();
    }

    // epilogue: add bias, vectorized float4 stores
    const int c0 = n0 + tx * 4;
    const int c1 = c0 + 64;
    float4 b0 = make_float4(0.f, 0.f, 0.f, 0.f);
    float4 b1 = make_float4(0.f, 0.f, 0.f, 0.f);
    if (c0 < G4) b0 = *(const float4*)&bias[c0];
    if (c1 < G4) b1 = *(const float4*)&bias[c1];

#pragma unroll
    for (int ri = 0; ri < 8; ri++) {
        int row = r0 + ((ri >> 2) * 64) + ty * 4 + (ri & 3);
        size_t base = (size_t)row * G4;
        if (c0 < G4) {
            float4 v = make_float4(acc[ri][0] + b0.x, acc[ri][1] + b0.y,
                                   acc[ri][2] + b0.z, acc[ri][3] + b0.w);
            *(float4*)&g_xpre[base + c0] = v;
        }
        if (c1 < G4) {
            float4 v = make_float4(acc[ri][4] + b1.x, acc[ri][5] + b1.y,
                                   acc[ri][6] + b1.z, acc[ri][7] + b1.w);
            *(float4*)&g_xpre[base + c1] = v;
        }
    }
}

// ---------------------------------------------------------------------------
// One LSTM timestep, fused GEMM + activations + masked state update.
// gates[b, g*H + j] = xpre[b,t,g*H+j] + sum_k h[b,k] * Wh[k, g*H+j]
// Block tile: 64 batch rows x 32 hidden cols x 4 gates. 256 threads.
// Thread tile: 4 batch x 2 hidden x 4 gates = 32 accumulators. KT=20.
// ---------------------------------------------------------------------------
__device__ __forceinline__ float sigmoidf_(float x) {
    return 1.f / (1.f + __expf(-x));
}
__device__ __forceinline__ float tanhf_(float x) {
    return 1.f - 2.f / (__expf(2.f * x) + 1.f);
}

__global__ __launch_bounds__(256) void step_kernel(
    const int*   __restrict__ lens,
    const float* __restrict__ Wh,
    int t, int par)
{
    __shared__ float hs[20][64];       // [k][b]
    __shared__ float ws[20][4][32];    // [k][gate][j]

    const float* __restrict__ hin  = g_h[par];
    float*       __restrict__ hout = g_h[par ^ 1];

    const int b0  = blockIdx.x * 64;
    const int j0  = blockIdx.y * 32;
    const int tid = threadIdx.x;
    const int tx  = tid & 15;         // hidden-col group (2 cols each)
    const int ty  = tid >> 4;         // batch-row group (4 rows each)

    float acc[4][2][4];               // [gate][jj][bi]
#pragma unroll
    for (int g = 0; g < 4; g++)
#pragma unroll
        for (int jj = 0; jj < 2; jj++)
#pragma unroll
            for (int bi = 0; bi < 4; bi++) acc[g][jj][bi] = 0.f;

    for (int k0 = 0; k0 < Hv; k0 += 20) {
#pragma unroll
        for (int r = 0; r < 5; r++) {
            int f  = r * 256 + tid;
            int bl = f & 63;
            int kl = f >> 6;
            hs[kl][bl] = hin[(b0 + bl) * Hv + k0 + kl];
        }
#pragma unroll
        for (int r = 0; r < 10; r++) {
            int f     = r * 256 + tid;
            int inner = f & 127;
            int kl    = f >> 7;
            int g     = inner >> 5;
            int jj    = inner & 31;
            int j     = j0 + jj;
            ws[kl][g][jj] = (j < Hv) ? Wh[(k0 + kl) * G4 + g * Hv + j] : 0.f;
        }
        __syncthreads();
#pragma unroll
        for (int k = 0; k < 20; k++) {
            float4 h4 = *(const float4*)&hs[k][ty * 4];
            float hv[4] = {h4.x, h4.y, h4.z, h4.w};
#pragma unroll
            for (int g = 0; g < 4; g++) {
                float2 w2 = *(const float2*)&ws[k][g][tx * 2];
#pragma unroll
                for (int bi = 0; bi < 4; bi++) {
                    acc[g][0][bi] = fmaf(hv[bi], w2.x, acc[g][0][bi]);
                    acc[g][1][bi] = fmaf(hv[bi], w2.y, acc[g][1][bi]);
                }
            }
        }
        __syncthreads();
    }

    // epilogue: activations + masked update
#pragma unroll
    for (int bi = 0; bi < 4; bi++) {
        const int  b = b0 + ty * 4 + bi;
        const bool m = (t < lens[b]);
#pragma unroll
        for (int jj = 0; jj < 2; jj++) {
            const int j = j0 + tx * 2 + jj;
            if (j >= Hv) continue;
            const size_t xbase = ((size_t)(b * Tv + t)) * G4 + j;
            float gi = acc[0][jj][bi] + g_xpre[xbase];
            float gf = acc[1][jj][bi] + g_xpre[xbase + Hv];
            float gg = acc[2][jj][bi] + g_xpre[xbase + 2 * Hv];
            float go = acc[3][jj][bi] + g_xpre[xbase + 3 * Hv];

            float iv = sigmoidf_(gi);
            float fv = sigmoidf_(gf);
            float gv = tanhf_(gg);
            float ov = sigmoidf_(go);

            const int hidx = b * Hv + j;
            float cold = g_c[hidx];
            float cnew = fv * cold + iv * gv;
            float hnew = ov * tanhf_(cnew);

            if (m) {
                g_c[hidx]  = cnew;
                hout[hidx] = hnew;
            } else {
                hout[hidx] = hin[hidx];
            }
        }
    }
}

// ---------------------------------------------------------------------------
// Output: logits[b, c] = sum_j h[b, j] * Wout[j, c] + bout[c]
// One warp per batch row. Final h lives in g_h[0] (80 steps, even parity).
// ---------------------------------------------------------------------------
__global__ void out_kernel(const float* __restrict__ Wout,
                           const float* __restrict__ bout,
                           float* __restrict__ out)
{
    int gwarp = (blockIdx.x * blockDim.x + threadIdx.x) >> 5;
    int lane  = threadIdx.x & 31;
    if (gwarp >= Bv) return;

    const float* h = &g_h[0][gwarp * Hv];
    float s0 = 0.f, s1 = 0.f, s2 = 0.f;
    for (int j = lane; j < Hv; j += 32) {
        float hv = h[j];
        s0 = fmaf(hv, Wout[j * 3 + 0], s0);
        s1 = fmaf(hv, Wout[j * 3 + 1], s1);
        s2 = fmaf(hv, Wout[j * 3 + 2], s2);
    }
#pragma unroll
    for (int off = 16; off > 0; off >>= 1) {
        s0 += __shfl_down_sync(0xffffffffu, s0, off);
        s1 += __shfl_down_sync(0xffffffffu, s1, off);
        s2 += __shfl_down_sync(0xffffffffu, s2, off);
    }
    if (lane == 0) {
        out[gwarp * 3 + 0] = s0 + bout[0];
        out[gwarp * 3 + 1] = s1 + bout[1];
        out[gwarp * 3 + 2] = s2 + bout[2];
    }
}

// ---------------------------------------------------------------------------
extern "C" void kernel_launch(void* const* d_in, const int* in_sizes, int n_in,
                              void* d_out, int out_size)
{
    const int*   sent = (const int*)  d_in[0];
    const int*   lens = (const int*)  d_in[1];
    const float* emb  = (const float*)d_in[2];
    const float* Wx   = (const float*)d_in[3];
    const float* Wh   = (const float*)d_in[4];
    const float* bias = (const float*)d_in[5];
    const float* Wout = (const float*)d_in[6];
    const float* bout = (const float*)d_in[7];
    float* out = (float*)d_out;

    // init states
    zero_kernel<<<(Bv * Hv + 255) / 256, 256>>>();

    // precompute x@Wx + b for all timesteps (gathered GEMM)
    dim3 pg(MROWS / 128, (G4 + 127) / 128);   // 640 x 10
    pre_kernel<<<pg, 256>>>(sent, lens, emb, Wx, bias);

    // sequential recurrence, double-buffered h
    dim3 sg(Bv / 64, (Hv + 31) / 32);         // 16 x 10
    for (int t = 0; t < Tv; t++) {
        step_kernel<<<sg, 256>>>(lens, Wh, t, t & 1);
    }

    // final projection
    out_kernel<<<(Bv * 32 + 127) / 128, 128>>>(Wout, bout, out);
}

// round 2
// speedup vs baseline: 1.7337x; 1.7337x over previous
#include <cuda_runtime.h>

// Problem dims (fixed by setup_inputs)
#define Bv   1024
#define Tv   80
#define Dv   300
#define Hv   300
#define G4   1200           // 4*H

// Scratch (device globals — no allocation allowed)
// xpre stored TRANSPOSED + permuted: xpre[t][n][p], p = length-sorted position
__device__ float g_xpre[(size_t)Tv * G4 * Bv];   // 393 MB
__device__ float g_hT[2][Hv * Bv];               // hT[k][p], double buffered
__device__ float g_cT[Hv * Bv];                  // cT[j][p]
__device__ int   g_perm[Bv];                     // perm[p] -> original batch
__device__ int   g_rank[Bv];                     // rank[b] -> sorted position
__device__ int   g_act[Tv];                      // #batches with len > t

// ---------------------------------------------------------------------------
// Deterministic counting rank by length (descending), plus active counts.
// One block, 1024 threads.
// ---------------------------------------------------------------------------
__global__ void init_kernel(const int* __restrict__ lens) {
    __shared__ int sl[Bv];
    const int tid = threadIdx.x;
    sl[tid] = lens[tid];
    __syncthreads();
    const int L = sl[tid];
    int r = 0;
    for (int b = 0; b < Bv; b++) {
        int L2 = sl[b];
        r += (L2 > L) || (L2 == L && b < tid);
    }
    g_rank[tid] = r;
    g_perm[r]   = tid;
    if (tid < Tv) {
        int c = 0;
        for (int b = 0; b < Bv; b++) c += (sl[b] > tid);
        g_act[tid] = c;
    }
}

__global__ void zero_kernel() {
    int i = blockIdx.x * blockDim.x + threadIdx.x;
    if (i < Hv * Bv) {
        g_hT[0][i] = 0.f;
        g_hT[1][i] = 0.f;
        g_cT[i]    = 0.f;
    }
}

// ---------------------------------------------------------------------------
// Precompute: xpre[t][n][p] = sum_k emb[sent[perm[p], t], k] * Wx[k, n] + b[n]
// grid = (p-tiles=8, n-tiles=10, t=80). Tile 128p x 128n, KT=20, 256 thr, 8x8.
// Skip tiles fully beyond the active prefix for this t.
// ---------------------------------------------------------------------------
__global__ __launch_bounds__(256) void pre_kernel(
    const int*   __restrict__ sent,
    const float* __restrict__ emb,
    const float* __restrict__ Wx,
    const float* __restrict__ bias)
{
    const int t  = blockIdx.z;
    const int p0 = blockIdx.x * 128;
    const int n0 = blockIdx.y * 128;
    if (p0 >= g_act[t]) return;     // whole tile masked -> never read

    __shared__ int   idxs[128];
    __shared__ float es[20][128];   // [k][p]
    __shared__ float ws[20][128];   // [k][n]

    const int tid = threadIdx.x;
    const int tx  = tid & 15;       // p group (4 each, x2 halves)
    const int ty  = tid >> 4;       // n group (4 each, x2 halves)

    if (tid < 128) idxs[tid] = sent[g_perm[p0 + tid] * Tv + t];
    __syncthreads();

    float acc[8][8];                // [ni][pi]
#pragma unroll
    for (int i = 0; i < 8; i++)
#pragma unroll
        for (int j = 0; j < 8; j++) acc[i][j] = 0.f;

    for (int k0 = 0; k0 < Dv; k0 += 20) {
#pragma unroll
        for (int r = 0; r < 10; r++) {
            int f  = r * 256 + tid;
            int rl = f & 127;
            int kl = f >> 7;
            es[kl][rl] = emb[(size_t)idxs[rl] * Dv + k0 + kl];
            int n = n0 + rl;
            ws[kl][rl] = (n < G4) ? Wx[(k0 + kl) * G4 + n] : 0.f;
        }
        __syncthreads();
#pragma unroll
        for (int k = 0; k < 20; k++) {
            float4 a0 = *(const float4*)&es[k][tx * 4];
            float4 a1 = *(const float4*)&es[k][tx * 4 + 64];
            float4 w0 = *(const float4*)&ws[k][ty * 4];
            float4 w1 = *(const float4*)&ws[k][ty * 4 + 64];
            float a[8] = {a0.x, a0.y, a0.z, a0.w, a1.x, a1.y, a1.z, a1.w};
            float w[8] = {w0.x, w0.y, w0.z, w0.w, w1.x, w1.y, w1.z, w1.w};
#pragma unroll
            for (int ni = 0; ni < 8; ni++)
#pragma unroll
                for (int pi = 0; pi < 8; pi++)
                    acc[ni][pi] = fmaf(w[ni], a[pi], acc[ni][pi]);
        }
        __syncthreads();
    }

    // store transposed: xpre[(t*G4 + n)*Bv + p], float4 along p
#pragma unroll
    for (int ni = 0; ni < 8; ni++) {
        int n = n0 + (ni >> 2) * 64 + ty * 4 + (ni & 3);
        if (n >= G4) continue;
        float bn = bias[n];
        size_t base = ((size_t)t * G4 + n) * Bv + p0;
        float4 v0 = make_float4(acc[ni][0] + bn, acc[ni][1] + bn,
                                acc[ni][2] + bn, acc[ni][3] + bn);
        float4 v1 = make_float4(acc[ni][4] + bn, acc[ni][5] + bn,
                                acc[ni][6] + bn, acc[ni][7] + bn);
        *(float4*)&g_xpre[base + tx * 4]      = v0;
        *(float4*)&g_xpre[base + tx * 4 + 64] = v1;
    }
}

// ---------------------------------------------------------------------------
// One LSTM timestep. Tile: 64 sorted-batch (p) x 16 hidden cols (j) x 4 gates.
// grid = (16 p-tiles, 19 j-tiles), 256 threads, 16 acc/thread (4p x 4g).
// Fully-inactive p-tiles just copy h forward (double-buffer consistency).
// ---------------------------------------------------------------------------
__device__ __forceinline__ float sigmoidf_(float x) {
    return 1.f / (1.f + __expf(-x));
}
__device__ __forceinline__ float tanhf_(float x) {
    return 1.f - 2.f / (__expf(2.f * x) + 1.f);
}

__global__ __launch_bounds__(256) void step_kernel(
    const float* __restrict__ Wh, int t, int par)
{
    const float* __restrict__ hin  = g_hT[par];
    float*       __restrict__ hout = g_hT[par ^ 1];

    const int p0   = blockIdx.x * 64;
    const int j0   = blockIdx.y * 16;
    const int tid  = threadIdx.x;
    const int pgrp = tid & 15;        // 4 consecutive p each
    const int jc   = tid >> 4;        // one j column
    const int j    = j0 + jc;
    const int act  = g_act[t];
    const int pb   = p0 + pgrp * 4;

    if (p0 >= act) {                  // inactive tile: copy h forward
        if (j < Hv)
            *(float4*)&hout[j * Bv + pb] = *(const float4*)&hin[j * Bv + pb];
        return;
    }

    __shared__ float hs[20][64];      // [k][p]
    __shared__ float ws[20][4][16];   // [k][gate][j]

    float4 acc[4];                    // per gate, 4 p-elements each
#pragma unroll
    for (int g = 0; g < 4; g++) acc[g] = make_float4(0.f, 0.f, 0.f, 0.f);

    for (int k0 = 0; k0 < Hv; k0 += 20) {
#pragma unroll
        for (int r = 0; r < 5; r++) {
            int f  = r * 256 + tid;
            int kl = f >> 6;
            int pp = f & 63;
            hs[kl][pp] = hin[(k0 + kl) * Bv + p0 + pp];
        }
#pragma unroll
        for (int r = 0; r < 5; r++) {
            int f     = r * 256 + tid;
            int kl    = f >> 6;
            int inner = f & 63;
            int g     = inner >> 4;
            int jj    = inner & 15;
            ws[kl][g][jj] = (j0 + jj < Hv) ? Wh[(k0 + kl) * G4 + g * Hv + j0 + jj]
                                           : 0.f;
        }
        __syncthreads();
#pragma unroll
        for (int k = 0; k < 20; k++) {
            float4 h4 = *(const float4*)&hs[k][pgrp * 4];
            float w0 = ws[k][0][jc], w1 = ws[k][1][jc];
            float w2 = ws[k][2][jc], w3 = ws[k][3][jc];
            acc[0].x = fmaf(w0, h4.x, acc[0].x);
            acc[0].y = fmaf(w0, h4.y, acc[0].y);
            acc[0].z = fmaf(w0, h4.z, acc[0].z);
            acc[0].w = fmaf(w0, h4.w, acc[0].w);
            acc[1].x = fmaf(w1, h4.x, acc[1].x);
            acc[1].y = fmaf(w1, h4.y, acc[1].y);
            acc[1].z = fmaf(w1, h4.z, acc[1].z);
            acc[1].w = fmaf(w1, h4.w, acc[1].w);
            acc[2].x = fmaf(w2, h4.x, acc[2].x);
            acc[2].y = fmaf(w2, h4.y, acc[2].y);
            acc[2].z = fmaf(w2, h4.z, acc[2].z);
            acc[2].w = fmaf(w2, h4.w, acc[2].w);
            acc[3].x = fmaf(w3, h4.x, acc[3].x);
            acc[3].y = fmaf(w3, h4.y, acc[3].y);
            acc[3].z = fmaf(w3, h4.z, acc[3].z);
            acc[3].w = fmaf(w3, h4.w, acc[3].w);
        }
        __syncthreads();
    }

    if (j >= Hv) return;

    // epilogue: gates = acc + xpre, activations, masked state update
    const size_t tb = (size_t)t * G4;
    float4 xi = *(const float4*)&g_xpre[(tb + 0 * Hv + j) * Bv + pb];
    float4 xf = *(const float4*)&g_xpre[(tb + 1 * Hv + j) * Bv + pb];
    float4 xg = *(const float4*)&g_xpre[(tb + 2 * Hv + j) * Bv + pb];
    float4 xo = *(const float4*)&g_xpre[(tb + 3 * Hv + j) * Bv + pb];
    float4 c4 = *(const float4*)&g_cT[j * Bv + pb];
    float4 h4 = *(const float4*)&hin[j * Bv + pb];

    float gi[4] = {acc[0].x + xi.x, acc[0].y + xi.y, acc[0].z + xi.z, acc[0].w + xi.w};
    float gf[4] = {acc[1].x + xf.x, acc[1].y + xf.y, acc[1].z + xf.z, acc[1].w + xf.w};
    float gg[4] = {acc[2].x + xg.x, acc[2].y + xg.y, acc[2].z + xg.z, acc[2].w + xg.w};
    float go[4] = {acc[3].x + xo.x, acc[3].y + xo.y, acc[3].z + xo.z, acc[3].w + xo.w};
    float cold[4] = {c4.x, c4.y, c4.z, c4.w};
    float hold[4] = {h4.x, h4.y, h4.z, h4.w};

    float hn[4], cn[4];
#pragma unroll
    for (int i = 0; i < 4; i++) {
        float iv = sigmoidf_(gi[i]);
        float fv = sigmoidf_(gf[i]);
        float gv = tanhf_(gg[i]);
        float ov = sigmoidf_(go[i]);
        float cnew = fv * cold[i] + iv * gv;
        float hnew = ov * tanhf_(cnew);
        bool m = (pb + i) < act;
        cn[i] = m ? cnew : cold[i];
        hn[i] = m ? hnew : hold[i];
    }
    *(float4*)&hout[j * Bv + pb] = make_float4(hn[0], hn[1], hn[2], hn[3]);
    *(float4*)&g_cT [j * Bv + pb] = make_float4(cn[0], cn[1], cn[2], cn[3]);
}

// ---------------------------------------------------------------------------
// Output: out[b, c] = sum_j hT[j, rank[b]] * Wout[j, c] + bout[c]
// One warp per batch row. Final h lives in g_hT[0] (80 steps, even parity).
// ---------------------------------------------------------------------------
__global__ void out_kernel(const float* __restrict__ Wout,
                           const float* __restrict__ bout,
                           float* __restrict__ out)
{
    int gwarp = (blockIdx.x * blockDim.x + threadIdx.x) >> 5;
    int lane  = threadIdx.x & 31;
    if (gwarp >= Bv) return;

    const int p = g_rank[gwarp];
    float s0 = 0.f, s1 = 0.f, s2 = 0.f;
    for (int jj = lane; jj < Hv; jj += 32) {
        float hv = g_hT[0][jj * Bv + p];
        s0 = fmaf(hv, Wout[jj * 3 + 0], s0);
        s1 = fmaf(hv, Wout[jj * 3 + 1], s1);
        s2 = fmaf(hv, Wout[jj * 3 + 2], s2);
    }
#pragma unroll
    for (int off = 16; off > 0; off >>= 1) {
        s0 += __shfl_down_sync(0xffffffffu, s0, off);
        s1 += __shfl_down_sync(0xffffffffu, s1, off);
        s2 += __shfl_down_sync(0xffffffffu, s2, off);
    }
    if (lane == 0) {
        out[gwarp * 3 + 0] = s0 + bout[0];
        out[gwarp * 3 + 1] = s1 + bout[1];
        out[gwarp * 3 + 2] = s2 + bout[2];
    }
}

// ---------------------------------------------------------------------------
extern "C" void kernel_launch(void* const* d_in, const int* in_sizes, int n_in,
                              void* d_out, int out_size)
{
    const int*   sent = (const int*)  d_in[0];
    const int*   lens = (const int*)  d_in[1];
    const float* emb  = (const float*)d_in[2];
    const float* Wx   = (const float*)d_in[3];
    const float* Wh   = (const float*)d_in[4];
    const float* bias = (const float*)d_in[5];
    const float* Wout = (const float*)d_in[6];
    const float* bout = (const float*)d_in[7];
    float* out = (float*)d_out;

    init_kernel<<<1, 1024>>>(lens);
    zero_kernel<<<(Hv * Bv + 255) / 256, 256>>>();

    // gathered GEMM, permuted + transposed output, tile-skips masked t
    dim3 pg(Bv / 128, (G4 + 127) / 128, Tv);   // 8 x 10 x 80
    pre_kernel<<<pg, 256>>>(sent, emb, Wx, bias);

    // sequential recurrence, double-buffered hT
    dim3 sg(Bv / 64, (Hv + 15) / 16);          // 16 x 19 = 304 blocks
    for (int t = 0; t < Tv; t++) {
        step_kernel<<<sg, 256>>>(Wh, t, t & 1);
    }

    out_kernel<<<(Bv * 32 + 127) / 128, 128>>>(Wout, bout, out);
}

// round 3
// speedup vs baseline: 1.9982x; 1.1526x over previous
#include <cuda_runtime.h>

// Problem dims (fixed by setup_inputs)
#define Bv   1024
#define Tv   80
#define Dv   300
#define Hv   300
#define G4   1200           // 4*H
#define NBLK 608            // persistent grid (co-residency guaranteed, 6/SM cap)
#define NTHR 128

// Scratch (device globals — no allocation allowed)
__device__ float g_xpre[(size_t)Tv * G4 * Bv];   // xpre[t][n][p]
__device__ float g_hT[2][Hv * Bv];               // hT[k][p], double buffered
__device__ float g_cT[Hv * Bv];                  // cT[j][p]
__device__ int   g_perm[Bv];
__device__ int   g_rank[Bv];
__device__ int   g_act[Tv];
__device__ unsigned g_bar_count;
__device__ unsigned g_bar_sense;

// ---------------------------------------------------------------------------
__global__ void init_kernel(const int* __restrict__ lens) {
    __shared__ int sl[Bv];
    const int tid = threadIdx.x;
    sl[tid] = lens[tid];
    __syncthreads();
    const int L = sl[tid];
    int r = 0;
    for (int b = 0; b < Bv; b++) {
        int L2 = sl[b];
        r += (L2 > L) || (L2 == L && b < tid);
    }
    g_rank[tid] = r;
    g_perm[r]   = tid;
    if (tid < Tv) {
        int c = 0;
        for (int b = 0; b < Bv; b++) c += (sl[b] > tid);
        g_act[tid] = c;
    }
    if (tid == 0) { g_bar_count = 0; g_bar_sense = 0; }
}

__global__ void zero_kernel() {
    int i = blockIdx.x * blockDim.x + threadIdx.x;
    if (i < Hv * Bv) {
        g_hT[0][i] = 0.f;
        g_hT[1][i] = 0.f;
        g_cT[i]    = 0.f;
    }
}

// ---------------------------------------------------------------------------
// Precompute xpre[t][n][p] (unchanged from R2 — near fp32 FMA peak already)
// ---------------------------------------------------------------------------
__global__ __launch_bounds__(256) void pre_kernel(
    const int*   __restrict__ sent,
    const float* __restrict__ emb,
    const float* __restrict__ Wx,
    const float* __restrict__ bias)
{
    const int t  = blockIdx.z;
    const int p0 = blockIdx.x * 128;
    const int n0 = blockIdx.y * 128;
    if (p0 >= g_act[t]) return;

    __shared__ int   idxs[128];
    __shared__ float es[20][128];
    __shared__ float ws[20][128];

    const int tid = threadIdx.x;
    const int tx  = tid & 15;
    const int ty  = tid >> 4;

    if (tid < 128) idxs[tid] = sent[g_perm[p0 + tid] * Tv + t];
    __syncthreads();

    float acc[8][8];
#pragma unroll
    for (int i = 0; i < 8; i++)
#pragma unroll
        for (int j = 0; j < 8; j++) acc[i][j] = 0.f;

    for (int k0 = 0; k0 < Dv; k0 += 20) {
#pragma unroll
        for (int r = 0; r < 10; r++) {
            int f  = r * 256 + tid;
            int rl = f & 127;
            int kl = f >> 7;
            es[kl][rl] = emb[(size_t)idxs[rl] * Dv + k0 + kl];
            int n = n0 + rl;
            ws[kl][rl] = (n < G4) ? Wx[(k0 + kl) * G4 + n] : 0.f;
        }
        __syncthreads();
#pragma unroll
        for (int k = 0; k < 20; k++) {
            float4 a0 = *(const float4*)&es[k][tx * 4];
            float4 a1 = *(const float4*)&es[k][tx * 4 + 64];
            float4 w0 = *(const float4*)&ws[k][ty * 4];
            float4 w1 = *(const float4*)&ws[k][ty * 4 + 64];
            float a[8] = {a0.x, a0.y, a0.z, a0.w, a1.x, a1.y, a1.z, a1.w};
            float w[8] = {w0.x, w0.y, w0.z, w0.w, w1.x, w1.y, w1.z, w1.w};
#pragma unroll
            for (int ni = 0; ni < 8; ni++)
#pragma unroll
                for (int pi = 0; pi < 8; pi++)
                    acc[ni][pi] = fmaf(w[ni], a[pi], acc[ni][pi]);
        }
        __syncthreads();
    }

#pragma unroll
    for (int ni = 0; ni < 8; ni++) {
        int n = n0 + (ni >> 2) * 64 + ty * 4 + (ni & 3);
        if (n >= G4) continue;
        float bn = bias[n];
        size_t base = ((size_t)t * G4 + n) * Bv + p0;
        float4 v0 = make_float4(acc[ni][0] + bn, acc[ni][1] + bn,
                                acc[ni][2] + bn, acc[ni][3] + bn);
        float4 v1 = make_float4(acc[ni][4] + bn, acc[ni][5] + bn,
                                acc[ni][6] + bn, acc[ni][7] + bn);
        *(float4*)&g_xpre[base + tx * 4]      = v0;
        *(float4*)&g_xpre[base + tx * 4 + 64] = v1;
    }
}

// ---------------------------------------------------------------------------
// Persistent LSTM recurrence: one launch, 80 steps, software grid barrier.
// ---------------------------------------------------------------------------
__device__ __forceinline__ float sigmoidf_(float x) {
    return 1.f / (1.f + __expf(-x));
}
__device__ __forceinline__ float tanhf_(float x) {
    return 1.f - 2.f / (__expf(2.f * x) + 1.f);
}

__device__ __forceinline__ void grid_barrier(unsigned target) {
    __threadfence();
    __syncthreads();
    if (threadIdx.x == 0) {
        if (atomicAdd(&g_bar_count, 1u) == NBLK - 1) {
            g_bar_count = 0;
            __threadfence();
            atomicExch(&g_bar_sense, target);
        } else {
            while (*(volatile unsigned*)&g_bar_sense < target) __nanosleep(64);
        }
    }
    __syncthreads();
}

// One tile of the step GEMM: 64 p  x  W j-cols  x  4 gates, 128 threads.
// Double-buffered smem, register prefetch, single sync per k-chunk (KT=20).
template<int W>
__device__ __forceinline__ void step_tile(
    float hs[2][20][64], float ws[2][20][8][4],
    const float* __restrict__ hin, float* __restrict__ hout,
    const float* __restrict__ Wh, int t, int p0, int j0, int act)
{
    constexpr int TPJ = NTHR / W;        // threads per j column
    constexpr int PPT = 64 / TPJ;        // p per thread (4 / 2 / 1)
    constexpr int WEL = 80 * W;          // ws elements per chunk
    constexpr int WLN = (WEL + NTHR - 1) / NTHR;
    const int tid  = threadIdx.x;
    const int pidx = tid % TPJ;
    const int jc   = tid / TPJ;
    const int j    = j0 + jc;

    float ph[10];
    float pw[WLN];

    auto load_c = [&](int k0) {
#pragma unroll
        for (int i = 0; i < 10; i++) {
            int f = i * NTHR + tid;
            ph[i] = __ldcg(&hin[(k0 + (f >> 6)) * Bv + p0 + (f & 63)]);
        }
#pragma unroll
        for (int i = 0; i < WLN; i++) {
            int idx = i * NTHR + tid;
            float v = 0.f;
            if (idx < WEL) {
                int kl  = idx / (4 * W);
                int rem = idx - kl * (4 * W);
                int jj  = rem >> 2;
                int g   = rem & 3;
                int col = j0 + jj;
                if (col < Hv) v = __ldg(&Wh[(k0 + kl) * G4 + g * Hv + col]);
            }
            pw[i] = v;
        }
    };
    auto store_c = [&](int buf) {
#pragma unroll
        for (int i = 0; i < 10; i++) {
            int f = i * NTHR + tid;
            hs[buf][f >> 6][f & 63] = ph[i];
        }
#pragma unroll
        for (int i = 0; i < WLN; i++) {
            int idx = i * NTHR + tid;
            if (idx < WEL) {
                int kl  = idx / (4 * W);
                int rem = idx - kl * (4 * W);
                ws[buf][kl][rem >> 2][rem & 3] = pw[i];
            }
        }
    };

    float acc[PPT][4];
#pragma unroll
    for (int p = 0; p < PPT; p++)
#pragma unroll
        for (int g = 0; g < 4; g++) acc[p][g] = 0.f;

    load_c(0);
    store_c(0);
    __syncthreads();

#pragma unroll 1
    for (int c = 0; c < 15; c++) {
        const int cur = c & 1;
        if (c < 14) load_c((c + 1) * 20);
#pragma unroll
        for (int k = 0; k < 20; k++) {
            float hv[PPT];
            if (PPT == 4) {
                float4 h4 = *(const float4*)&hs[cur][k][pidx * 4];
                hv[0] = h4.x; hv[1] = h4.y; hv[2] = h4.z; hv[3] = h4.w;
            } else if (PPT == 2) {
                float2 h2 = *(const float2*)&hs[cur][k][pidx * 2];
                hv[0] = h2.x; hv[1] = h2.y;
            } else {
                hv[0] = hs[cur][k][pidx];
            }
            float4 w4 = *(const float4*)&ws[cur][k][jc][0];
            float wg[4] = {w4.x, w4.y, w4.z, w4.w};
#pragma unroll
            for (int p = 0; p < PPT; p++)
#pragma unroll
                for (int g = 0; g < 4; g++)
                    acc[p][g] = fmaf(hv[p], wg[g], acc[p][g]);
        }
        if (c < 14) { store_c(cur ^ 1); __syncthreads(); }
    }

    if (j >= Hv) return;

    const size_t tb = (size_t)t * G4;
    const int pb = p0 + pidx * PPT;
#pragma unroll
    for (int p = 0; p < PPT; p++) {
        const int pp = pb + p;
        float gi = acc[p][0] + __ldg(&g_xpre[(tb + 0 * Hv + j) * Bv + pp]);
        float gf = acc[p][1] + __ldg(&g_xpre[(tb + 1 * Hv + j) * Bv + pp]);
        float gg = acc[p][2] + __ldg(&g_xpre[(tb + 2 * Hv + j) * Bv + pp]);
        float go = acc[p][3] + __ldg(&g_xpre[(tb + 3 * Hv + j) * Bv + pp]);

        float iv = sigmoidf_(gi);
        float fv = sigmoidf_(gf);
        float gv = tanhf_(gg);
        float ov = sigmoidf_(go);

        const int hi = j * Bv + pp;
        float cold = __ldcg(&g_cT[hi]);
        float cnew = fv * cold + iv * gv;
        float hnew = ov * tanhf_(cnew);
        const bool m = pp < act;
        __stcg(&g_cT[hi], m ? cnew : cold);
        __stcg(&hout[hi], m ? hnew : __ldcg(&hin[hi]));
    }
}

__global__ __launch_bounds__(NTHR, 6) void lstm_kernel(const float* __restrict__ Wh)
{
    __shared__ float hs[2][20][64];
    __shared__ float ws[2][20][8][4];
    const int bid = blockIdx.x;
    const int tid = threadIdx.x;
    int prev_pad = Bv;

#pragma unroll 1
    for (int t = 0; t < Tv; t++) {
        const int par = t & 1;
        const float* hin  = g_hT[par];
        float*       hout = g_hT[par ^ 1];
        const int act = g_act[t];
        const int na  = (act + 63) >> 6;
        const int pad = na << 6;

        // copy forward only the newly-inactive band [pad, prev_pad)
        if (pad < prev_pad) {
            int n4    = (prev_pad - pad) >> 2;
            int total = Hv * n4;
            for (int idx = bid * NTHR + tid; idx < total; idx += NBLK * NTHR) {
                int jj  = idx / n4;
                int po  = idx - jj * n4;
                int off = jj * Bv + pad + (po << 2);
                float4 v = __ldcg((const float4*)&hin[off]);
                __stcg((float4*)&hout[off], v);
            }
        }
        prev_pad = pad;

        // dynamic re-tiling: j-width shrinks as active prefix shrinks
        int w, njt;
        if      (na >= 9) { w = 8; njt = 38;  }
        else if (na >= 5) { w = 4; njt = 75;  }
        else              { w = 2; njt = 150; }

        if (bid < na * njt) {
            int pt = bid / njt;
            int jt = bid - pt * njt;
            if (w == 8)
                step_tile<8>(hs, ws, hin, hout, Wh, t, pt * 64, jt * 8, act);
            else if (w == 4)
                step_tile<4>(hs, ws, hin, hout, Wh, t, pt * 64, jt * 4, act);
            else
                step_tile<2>(hs, ws, hin, hout, Wh, t, pt * 64, jt * 2, act);
        }
        grid_barrier(t + 1);
    }
}

// ---------------------------------------------------------------------------
__global__ void out_kernel(const float* __restrict__ Wout,
                           const float* __restrict__ bout,
                           float* __restrict__ out)
{
    int gwarp = (blockIdx.x * blockDim.x + threadIdx.x) >> 5;
    int lane  = threadIdx.x & 31;
    if (gwarp >= Bv) return;

    const int p = g_rank[gwarp];
    float s0 = 0.f, s1 = 0.f, s2 = 0.f;
    for (int jj = lane; jj < Hv; jj += 32) {
        float hv = g_hT[0][jj * Bv + p];
        s0 = fmaf(hv, Wout[jj * 3 + 0], s0);
        s1 = fmaf(hv, Wout[jj * 3 + 1], s1);
        s2 = fmaf(hv, Wout[jj * 3 + 2], s2);
    }
#pragma unroll
    for (int off = 16; off > 0; off >>= 1) {
        s0 += __shfl_down_sync(0xffffffffu, s0, off);
        s1 += __shfl_down_sync(0xffffffffu, s1, off);
        s2 += __shfl_down_sync(0xffffffffu, s2, off);
    }
    if (lane == 0) {
        out[gwarp * 3 + 0] = s0 + bout[0];
        out[gwarp * 3 + 1] = s1 + bout[1];
        out[gwarp * 3 + 2] = s2 + bout[2];
    }
}

// ---------------------------------------------------------------------------
extern "C" void kernel_launch(void* const* d_in, const int* in_sizes, int n_in,
                              void* d_out, int out_size)
{
    const int*   sent = (const int*)  d_in[0];
    const int*   lens = (const int*)  d_in[1];
    const float* emb  = (const float*)d_in[2];
    const float* Wx   = (const float*)d_in[3];
    const float* Wh   = (const float*)d_in[4];
    const float* bias = (const float*)d_in[5];
    const float* Wout = (const float*)d_in[6];
    const float* bout = (const float*)d_in[7];
    float* out = (float*)d_out;

    init_kernel<<<1, 1024>>>(lens);
    zero_kernel<<<(Hv * Bv + 255) / 256, 256>>>();

    dim3 pg(Bv / 128, (G4 + 127) / 128, Tv);   // 8 x 10 x 80
    pre_kernel<<<pg, 256>>>(sent, emb, Wx, bias);

    // one persistent launch for all 80 timesteps
    lstm_kernel<<<NBLK, NTHR>>>(Wh);

    out_kernel<<<(Bv * 32 + 127) / 128, 128>>>(Wout, bout, out);
}